// round 10
// baseline (speedup 1.0000x reference)
#include <cuda_runtime.h>
#include <cstdint>

// SoftCountPixels: Y[b,p] = (1/(H*W)) * sum_{h,w} exp(-||x[b,:,h,w] - P[p,:]||_2 / 0.6)
// x: (16, 3, 256, 256) f32 planar; P: (32, 3) f32; out: (16, 32) f32
//
// exp(-d/0.6) = ex2(-sqrt(K2*d^2)), K2=(log2e/0.6)^2 (pre-scaled quadratic form).
// R10 = exact R7 body (packed f32x2 pair math, 444-block perfectly balanced
// flat partition, separate sqrt/ex2 intrinsics — measured best at 22.0us)
//  + eps-in-cck replacing fabs (R9-verified alu% reduction; worst-case fp
//    cancellation ~6e-6 << 3e-5, so s>0 always; error in exp <= ~2e-5 rel)
//  + single-launch scratch+ticket finisher (R9-verified bench win, no
//    zero-out prologue node).
// NO unroll-2, NO fused multi-op asm block (R9's kernel regression suspects).

#define B 16
#define HW (256 * 256)
#define HW4 (HW / 4)             // 16384 = 2^14 vec4 per channel plane
#define HW4_SHIFT 14
#define NPRO 32
#define PPT 4                    // protos per thread
#define PGROUPS (NPRO / PPT)     // 8
#define NCOMBO (B * PGROUPS)     // 128
#define THREADS 256
#define NBLOCKS 444              // 148 SMs * 3 CTAs -> one perfectly balanced wave
#define TOTAL_UNITS ((unsigned long long)NCOMBO * HW4)   // 2,097,152

#define K2 5.781580510735007f    // (log2(e)/0.6)^2
#define EPS_S 3e-5f              // positivity guard for the quadratic form

__device__ float    g_scratch[B * NPRO];   // zero-initialized at module load
__device__ unsigned g_ticket = 0;

__device__ __forceinline__ float fast_sqrt(float v) {
    float r;
    asm("sqrt.approx.f32 %0, %1;" : "=f"(r) : "f"(v));
    return r;
}
__device__ __forceinline__ float fast_ex2(float v) {
    float r;
    asm("ex2.approx.f32 %0, %1;" : "=f"(r) : "f"(v));
    return r;
}

// ---- packed f32x2 helpers ----
__device__ __forceinline__ uint64_t pack2(float lo, float hi) {
    uint64_t r;
    asm("mov.b64 %0, {%1, %2};" : "=l"(r) : "f"(lo), "f"(hi));
    return r;
}
__device__ __forceinline__ void unpack2(uint64_t v, float& lo, float& hi) {
    asm("mov.b64 {%0, %1}, %2;" : "=f"(lo), "=f"(hi) : "l"(v));
}
__device__ __forceinline__ uint64_t fma2(uint64_t a, uint64_t b, uint64_t c) {
    uint64_t r;
    asm("fma.rn.f32x2 %0, %1, %2, %3;" : "=l"(r) : "l"(a), "l"(b), "l"(c));
    return r;
}
__device__ __forceinline__ uint64_t add2(uint64_t a, uint64_t b) {
    uint64_t r;
    asm("add.rn.f32x2 %0, %1, %2;" : "=l"(r) : "l"(a), "l"(b));
    return r;
}
__device__ __forceinline__ uint64_t mul2(uint64_t a, uint64_t b) {
    uint64_t r;
    asm("mul.rn.f32x2 %0, %1, %2;" : "=l"(r) : "l"(a), "l"(b));
    return r;
}

__global__ __launch_bounds__(THREADS, 3)
void softcount_kernel(const float* __restrict__ x,
                      const float* __restrict__ P,
                      float* __restrict__ out) {
    const int tid  = threadIdx.x;
    const int lane = tid & 31;
    const unsigned long long bid = blockIdx.x;

    // This block's contiguous range of global vec4-units.
    unsigned long long u0 = (bid * TOTAL_UNITS) / NBLOCKS;
    const unsigned long long u1 = ((bid + 1) * TOTAL_UNITS) / NBLOCKS;

    while (u0 < u1) {
        const unsigned combo = (unsigned)(u0 >> HW4_SHIFT);   // 0..127
        const unsigned long long combo_end = (unsigned long long)(combo + 1) << HW4_SHIFT;
        const unsigned long long seg_end = (u1 < combo_end) ? u1 : combo_end;

        const int pg = (int)(combo >> 4);   // 0..7
        const int b  = (int)(combo & 15);   // 0..15

        // Packed (broadcast) per-proto constants, pre-scaled by K2, eps-biased.
        uint64_t qk0[PPT], qk1[PPT], qk2[PPT], cck[PPT];
        float acc[PPT];
#pragma unroll
        for (int i = 0; i < PPT; i++) {
            const int p = pg * PPT + i;
            const float p0 = __ldg(&P[p * 3 + 0]);
            const float p1 = __ldg(&P[p * 3 + 1]);
            const float p2 = __ldg(&P[p * 3 + 2]);
            const float q0 = -2.0f * K2 * p0;
            const float q1 = -2.0f * K2 * p1;
            const float q2 = -2.0f * K2 * p2;
            const float cc = K2 * (p0 * p0 + p1 * p1 + p2 * p2) + EPS_S;
            qk0[i] = pack2(q0, q0);
            qk1[i] = pack2(q1, q1);
            qk2[i] = pack2(q2, q2);
            cck[i] = pack2(cc, cc);
            acc[i] = 0.0f;
        }
        const uint64_t K2_2 = pack2(K2, K2);

        // Local vec4 index range within this combo's image.
        const int vs = (int)(u0 & (HW4 - 1));
        const int ve = (int)(seg_end - ((unsigned long long)combo << HW4_SHIFT));

        const ulonglong2* xb = (const ulonglong2*)(x + (size_t)b * 3 * HW);

        for (int v = vs + tid; v < ve; v += THREADS) {
            const ulonglong2 c0 = xb[v];              // ch0: pixels(0,1),(2,3) packed
            const ulonglong2 c1 = xb[v + HW4];        // ch1
            const ulonglong2 c2 = xb[v + 2 * HW4];    // ch2

            // ---- pixel pair (0,1) ----
            {
                const uint64_t X0 = c0.x, X1 = c1.x, X2 = c2.x;
                uint64_t xx = mul2(X0, X0);
                xx = fma2(X1, X1, xx);
                xx = fma2(X2, X2, xx);
                const uint64_t xxk = mul2(K2_2, xx);
#pragma unroll
                for (int i = 0; i < PPT; i++) {
                    uint64_t t = add2(cck[i], xxk);
                    t = fma2(qk0[i], X0, t);
                    t = fma2(qk1[i], X1, t);
                    t = fma2(qk2[i], X2, t);
                    float ta, tb;
                    unpack2(t, ta, tb);
                    acc[i] += fast_ex2(-fast_sqrt(ta));
                    acc[i] += fast_ex2(-fast_sqrt(tb));
                }
            }
            // ---- pixel pair (2,3) ----
            {
                const uint64_t X0 = c0.y, X1 = c1.y, X2 = c2.y;
                uint64_t xx = mul2(X0, X0);
                xx = fma2(X1, X1, xx);
                xx = fma2(X2, X2, xx);
                const uint64_t xxk = mul2(K2_2, xx);
#pragma unroll
                for (int i = 0; i < PPT; i++) {
                    uint64_t t = add2(cck[i], xxk);
                    t = fma2(qk0[i], X0, t);
                    t = fma2(qk1[i], X1, t);
                    t = fma2(qk2[i], X2, t);
                    float ta, tb;
                    unpack2(t, ta, tb);
                    acc[i] += fast_ex2(-fast_sqrt(ta));
                    acc[i] += fast_ex2(-fast_sqrt(tb));
                }
            }
        }

        // Flush this segment into scratch: warp shuffle + 1 atomic per (warp, proto).
#pragma unroll
        for (int i = 0; i < PPT; i++) {
            float v = acc[i];
#pragma unroll
            for (int off = 16; off > 0; off >>= 1)
                v += __shfl_xor_sync(0xFFFFFFFFu, v, off);
            if (lane == 0)
                atomicAdd(&g_scratch[b * NPRO + pg * PPT + i], v);
        }

        u0 = seg_end;
    }

    // ---- last-block finisher: scale scratch into d_out, reset state ----
    __threadfence();
    __shared__ unsigned is_last;
    if (tid == 0) {
        const unsigned t = atomicAdd(&g_ticket, 1u);
        is_last = (t == NBLOCKS - 1) ? 1u : 0u;
    }
    __syncthreads();
    if (is_last) {
        __threadfence();  // all blocks' scratch atomics visible
        for (int i = tid; i < B * NPRO; i += THREADS) {
            out[i] = g_scratch[i] * (1.0f / (float)HW);
            g_scratch[i] = 0.0f;          // reset for next graph replay
        }
        __syncthreads();
        if (tid == 0) g_ticket = 0u;      // reset ticket
    }
}

extern "C" void kernel_launch(void* const* d_in, const int* in_sizes, int n_in,
                              void* d_out, int out_size) {
    const float* x = (const float*)d_in[0];
    const float* P = (const float*)d_in[1];
    float* out = (float*)d_out;

    softcount_kernel<<<NBLOCKS, THREADS>>>(x, P, out);
}

// round 11
// speedup vs baseline: 1.1265x; 1.1265x over previous
#include <cuda_runtime.h>
#include <cuda_fp16.h>
#include <cstdint>

// SoftCountPixels: Y[b,p] = (1/(H*W)) * sum_{h,w} exp(-||x[b,:,h,w] - P[p,:]||_2 / 0.6)
// x: (16, 3, 256, 256) f32 planar; P: (32, 3) f32; out: (16, 32) f32
//
// exp(-d/0.6) = ex2(-sqrt(K2*d^2)), K2=(log2e/0.6)^2 (pre-scaled quadratic form,
// eps-biased so s>0 always -> no fabs).
// R11 KEY CHANGE: halve the EX2 MUFU count with ex2.approx.f16x2 — two
// exponentials per MUFU op. Per 2 (pixel,proto) pairs:
//   2x MUFU.SQRT(f32) -> cvt.rn.f16x2.f32 (pack) -> XOR 0x80008000 (negate
//   both halves, one LOP3) -> ex2.approx.f16x2 (ONE MUFU) -> add.rn.f16x2.
// MUFU/pair: 2.0 -> 1.5 (floor 28.3K -> 21.3K SMSP-cycles); EX2+FNEG+FADD
// (3 slots/pair) -> 1.5 slots/pair.
// Precision: half2 accumulators hold <= 38 terms/lane (<=19 loop iters x 2);
// rounding random-walk ~1e-4 rel on Y, term quantization ~5e-4 rel averaging
// out over 65536 samples — well under the 1e-3 gate.
// Base kept from best lineage: packed f32x2 quadratic form, 444-block
// balanced flat partition, single-launch scratch+ticket finisher.

#define B 16
#define HW (256 * 256)
#define HW4 (HW / 4)             // 16384 = 2^14 vec4 per channel plane
#define HW4_SHIFT 14
#define NPRO 32
#define PPT 4                    // protos per thread
#define PGROUPS (NPRO / PPT)     // 8
#define NCOMBO (B * PGROUPS)     // 128
#define THREADS 256
#define NBLOCKS 444              // 148 SMs * 3 CTAs -> one perfectly balanced wave
#define TOTAL_UNITS ((unsigned long long)NCOMBO * HW4)   // 2,097,152

#define K2 5.781580510735007f    // (log2(e)/0.6)^2
#define EPS_S 3e-5f              // positivity guard for the quadratic form

__device__ float    g_scratch[B * NPRO];   // zero-initialized at module load
__device__ unsigned g_ticket = 0;

__device__ __forceinline__ float fast_sqrt(float v) {
    float r;
    asm("sqrt.approx.f32 %0, %1;" : "=f"(r) : "f"(v));
    return r;
}

// pack two f32 into f16x2 (one F2FP)
__device__ __forceinline__ uint32_t cvt_f16x2(float a, float b) {
    uint32_t h;
    asm("cvt.rn.f16x2.f32 %0, %1, %2;" : "=r"(h) : "f"(b), "f"(a));
    return h;
}
// two exponentials in ONE MUFU op
__device__ __forceinline__ uint32_t ex2_h2(uint32_t h) {
    uint32_t e;
    asm("ex2.approx.f16x2 %0, %1;" : "=r"(e) : "r"(h));
    return e;
}
__device__ __forceinline__ uint32_t hadd2u(uint32_t a, uint32_t b) {
    uint32_t r;
    asm("add.rn.f16x2 %0, %1, %2;" : "=r"(r) : "r"(a), "r"(b));
    return r;
}

// ---- packed f32x2 helpers ----
__device__ __forceinline__ uint64_t pack2(float lo, float hi) {
    uint64_t r;
    asm("mov.b64 %0, {%1, %2};" : "=l"(r) : "f"(lo), "f"(hi));
    return r;
}
__device__ __forceinline__ void unpack2(uint64_t v, float& lo, float& hi) {
    asm("mov.b64 {%0, %1}, %2;" : "=f"(lo), "=f"(hi) : "l"(v));
}
__device__ __forceinline__ uint64_t fma2(uint64_t a, uint64_t b, uint64_t c) {
    uint64_t r;
    asm("fma.rn.f32x2 %0, %1, %2, %3;" : "=l"(r) : "l"(a), "l"(b), "l"(c));
    return r;
}
__device__ __forceinline__ uint64_t add2(uint64_t a, uint64_t b) {
    uint64_t r;
    asm("add.rn.f32x2 %0, %1, %2;" : "=l"(r) : "l"(a), "l"(b));
    return r;
}
__device__ __forceinline__ uint64_t mul2(uint64_t a, uint64_t b) {
    uint64_t r;
    asm("mul.rn.f32x2 %0, %1, %2;" : "=l"(r) : "l"(a), "l"(b));
    return r;
}

__global__ __launch_bounds__(THREADS, 3)
void softcount_kernel(const float* __restrict__ x,
                      const float* __restrict__ P,
                      float* __restrict__ out) {
    const int tid  = threadIdx.x;
    const int lane = tid & 31;
    const unsigned long long bid = blockIdx.x;

    // This block's contiguous range of global vec4-units.
    unsigned long long u0 = (bid * TOTAL_UNITS) / NBLOCKS;
    const unsigned long long u1 = ((bid + 1) * TOTAL_UNITS) / NBLOCKS;

    while (u0 < u1) {
        const unsigned combo = (unsigned)(u0 >> HW4_SHIFT);   // 0..127
        const unsigned long long combo_end = (unsigned long long)(combo + 1) << HW4_SHIFT;
        const unsigned long long seg_end = (u1 < combo_end) ? u1 : combo_end;

        const int pg = (int)(combo >> 4);   // 0..7
        const int b  = (int)(combo & 15);   // 0..15

        // Packed (broadcast) per-proto constants, pre-scaled by K2, eps-biased.
        uint64_t qk0[PPT], qk1[PPT], qk2[PPT], cck[PPT];
        uint32_t hacc[PPT];                 // half2 accumulators (+0,+0)
#pragma unroll
        for (int i = 0; i < PPT; i++) {
            const int p = pg * PPT + i;
            const float p0 = __ldg(&P[p * 3 + 0]);
            const float p1 = __ldg(&P[p * 3 + 1]);
            const float p2 = __ldg(&P[p * 3 + 2]);
            const float q0 = -2.0f * K2 * p0;
            const float q1 = -2.0f * K2 * p1;
            const float q2 = -2.0f * K2 * p2;
            const float cc = K2 * (p0 * p0 + p1 * p1 + p2 * p2) + EPS_S;
            qk0[i] = pack2(q0, q0);
            qk1[i] = pack2(q1, q1);
            qk2[i] = pack2(q2, q2);
            cck[i] = pack2(cc, cc);
            hacc[i] = 0u;
        }
        const uint64_t K2_2 = pack2(K2, K2);

        // Local vec4 index range within this combo's image.
        const int vs = (int)(u0 & (HW4 - 1));
        const int ve = (int)(seg_end - ((unsigned long long)combo << HW4_SHIFT));

        const ulonglong2* xb = (const ulonglong2*)(x + (size_t)b * 3 * HW);

        for (int v = vs + tid; v < ve; v += THREADS) {
            const ulonglong2 c0 = xb[v];              // ch0: pixels(0,1),(2,3) packed
            const ulonglong2 c1 = xb[v + HW4];        // ch1
            const ulonglong2 c2 = xb[v + 2 * HW4];    // ch2

            // ---- pixel pair (0,1) ----
            {
                const uint64_t X0 = c0.x, X1 = c1.x, X2 = c2.x;
                uint64_t xx = mul2(X0, X0);
                xx = fma2(X1, X1, xx);
                xx = fma2(X2, X2, xx);
                const uint64_t xxk = mul2(K2_2, xx);
#pragma unroll
                for (int i = 0; i < PPT; i++) {
                    uint64_t t = add2(cck[i], xxk);
                    t = fma2(qk0[i], X0, t);
                    t = fma2(qk1[i], X1, t);
                    t = fma2(qk2[i], X2, t);
                    float ta, tb;
                    unpack2(t, ta, tb);
                    const float ra = fast_sqrt(ta);        // MUFU.SQRT
                    const float rb = fast_sqrt(tb);        // MUFU.SQRT
                    uint32_t h = cvt_f16x2(ra, rb);        // F2FP pack
                    h ^= 0x80008000u;                      // negate both halves
                    hacc[i] = hadd2u(hacc[i], ex2_h2(h));  // ONE MUFU EX2 + HADD2
                }
            }
            // ---- pixel pair (2,3) ----
            {
                const uint64_t X0 = c0.y, X1 = c1.y, X2 = c2.y;
                uint64_t xx = mul2(X0, X0);
                xx = fma2(X1, X1, xx);
                xx = fma2(X2, X2, xx);
                const uint64_t xxk = mul2(K2_2, xx);
#pragma unroll
                for (int i = 0; i < PPT; i++) {
                    uint64_t t = add2(cck[i], xxk);
                    t = fma2(qk0[i], X0, t);
                    t = fma2(qk1[i], X1, t);
                    t = fma2(qk2[i], X2, t);
                    float ta, tb;
                    unpack2(t, ta, tb);
                    const float ra = fast_sqrt(ta);
                    const float rb = fast_sqrt(tb);
                    uint32_t h = cvt_f16x2(ra, rb);
                    h ^= 0x80008000u;
                    hacc[i] = hadd2u(hacc[i], ex2_h2(h));
                }
            }
        }

        // Flush this segment into scratch: half2 -> f32, warp shuffle,
        // 1 atomic per (warp, proto).
#pragma unroll
        for (int i = 0; i < PPT; i++) {
            const __half2 h = *reinterpret_cast<const __half2*>(&hacc[i]);
            const float2 f = __half22float2(h);
            float v = f.x + f.y;
#pragma unroll
            for (int off = 16; off > 0; off >>= 1)
                v += __shfl_xor_sync(0xFFFFFFFFu, v, off);
            if (lane == 0)
                atomicAdd(&g_scratch[b * NPRO + pg * PPT + i], v);
        }

        u0 = seg_end;
    }

    // ---- last-block finisher: scale scratch into d_out, reset state ----
    __threadfence();
    __shared__ unsigned is_last;
    if (tid == 0) {
        const unsigned t = atomicAdd(&g_ticket, 1u);
        is_last = (t == NBLOCKS - 1) ? 1u : 0u;
    }
    __syncthreads();
    if (is_last) {
        __threadfence();  // all blocks' scratch atomics visible
        for (int i = tid; i < B * NPRO; i += THREADS) {
            out[i] = g_scratch[i] * (1.0f / (float)HW);
            g_scratch[i] = 0.0f;          // reset for next graph replay
        }
        __syncthreads();
        if (tid == 0) g_ticket = 0u;      // reset ticket
    }
}

extern "C" void kernel_launch(void* const* d_in, const int* in_sizes, int n_in,
                              void* d_out, int out_size) {
    const float* x = (const float*)d_in[0];
    const float* P = (const float*)d_in[1];
    float* out = (float*)d_out;

    softcount_kernel<<<NBLOCKS, THREADS>>>(x, P, out);
}

// round 12
// speedup vs baseline: 1.1391x; 1.0111x over previous
#include <cuda_runtime.h>
#include <cuda_fp16.h>
#include <cstdint>

// SoftCountPixels: Y[b,p] = (1/(H*W)) * sum_{h,w} exp(-||x[b,:,h,w] - P[p,:]||_2 / 0.6)
// x: (16, 3, 256, 256) f32 planar; P: (32, 3) f32; out: (16, 32) f32
//
// exp(-d/0.6) = ex2(-sqrt(K2*d^2)), K2=(log2e/0.6)^2 (pre-scaled quadratic form,
// eps-biased so s>0 -> no fabs). EX2 done as ex2.approx.f16x2: two exponentials
// per MUFU op (R11-verified: issue 66->50%, rel_err 3.7e-4 passes).
// R12 ONE CHANGE: 4 CTAs/SM. regs=64 is exactly the 4-CTA budget;
// __launch_bounds__(256,4) + 592 balanced blocks -> 8 warps/SMSP to cover the
// sqrt->cvt->ex2 dependency chain that currently caps issue at 50%.

#define B 16
#define HW (256 * 256)
#define HW4 (HW / 4)             // 16384 = 2^14 vec4 per channel plane
#define HW4_SHIFT 14
#define NPRO 32
#define PPT 4                    // protos per thread
#define PGROUPS (NPRO / PPT)     // 8
#define NCOMBO (B * PGROUPS)     // 128
#define THREADS 256
#define NBLOCKS (148 * 4)        // 592: one perfectly balanced wave @ 4 CTA/SM
#define TOTAL_UNITS ((unsigned long long)NCOMBO * HW4)   // 2,097,152

#define K2 5.781580510735007f    // (log2(e)/0.6)^2
#define EPS_S 3e-5f              // positivity guard for the quadratic form

__device__ float    g_scratch[B * NPRO];   // zero-initialized at module load
__device__ unsigned g_ticket = 0;

__device__ __forceinline__ float fast_sqrt(float v) {
    float r;
    asm("sqrt.approx.f32 %0, %1;" : "=f"(r) : "f"(v));
    return r;
}

// pack two f32 into f16x2 (one F2FP)
__device__ __forceinline__ uint32_t cvt_f16x2(float a, float b) {
    uint32_t h;
    asm("cvt.rn.f16x2.f32 %0, %1, %2;" : "=r"(h) : "f"(b), "f"(a));
    return h;
}
// two exponentials in ONE MUFU op
__device__ __forceinline__ uint32_t ex2_h2(uint32_t h) {
    uint32_t e;
    asm("ex2.approx.f16x2 %0, %1;" : "=r"(e) : "r"(h));
    return e;
}
__device__ __forceinline__ uint32_t hadd2u(uint32_t a, uint32_t b) {
    uint32_t r;
    asm("add.rn.f16x2 %0, %1, %2;" : "=r"(r) : "r"(a), "r"(b));
    return r;
}

// ---- packed f32x2 helpers ----
__device__ __forceinline__ uint64_t pack2(float lo, float hi) {
    uint64_t r;
    asm("mov.b64 %0, {%1, %2};" : "=l"(r) : "f"(lo), "f"(hi));
    return r;
}
__device__ __forceinline__ void unpack2(uint64_t v, float& lo, float& hi) {
    asm("mov.b64 {%0, %1}, %2;" : "=f"(lo), "=f"(hi) : "l"(v));
}
__device__ __forceinline__ uint64_t fma2(uint64_t a, uint64_t b, uint64_t c) {
    uint64_t r;
    asm("fma.rn.f32x2 %0, %1, %2, %3;" : "=l"(r) : "l"(a), "l"(b), "l"(c));
    return r;
}
__device__ __forceinline__ uint64_t add2(uint64_t a, uint64_t b) {
    uint64_t r;
    asm("add.rn.f32x2 %0, %1, %2;" : "=l"(r) : "l"(a), "l"(b));
    return r;
}
__device__ __forceinline__ uint64_t mul2(uint64_t a, uint64_t b) {
    uint64_t r;
    asm("mul.rn.f32x2 %0, %1, %2;" : "=l"(r) : "l"(a), "l"(b));
    return r;
}

__global__ __launch_bounds__(THREADS, 4)
void softcount_kernel(const float* __restrict__ x,
                      const float* __restrict__ P,
                      float* __restrict__ out) {
    const int tid  = threadIdx.x;
    const int lane = tid & 31;
    const unsigned long long bid = blockIdx.x;

    // This block's contiguous range of global vec4-units.
    unsigned long long u0 = (bid * TOTAL_UNITS) / NBLOCKS;
    const unsigned long long u1 = ((bid + 1) * TOTAL_UNITS) / NBLOCKS;

    while (u0 < u1) {
        const unsigned combo = (unsigned)(u0 >> HW4_SHIFT);   // 0..127
        const unsigned long long combo_end = (unsigned long long)(combo + 1) << HW4_SHIFT;
        const unsigned long long seg_end = (u1 < combo_end) ? u1 : combo_end;

        const int pg = (int)(combo >> 4);   // 0..7
        const int b  = (int)(combo & 15);   // 0..15

        // Packed (broadcast) per-proto constants, pre-scaled by K2, eps-biased.
        uint64_t qk0[PPT], qk1[PPT], qk2[PPT], cck[PPT];
        uint32_t hacc[PPT];                 // half2 accumulators
#pragma unroll
        for (int i = 0; i < PPT; i++) {
            const int p = pg * PPT + i;
            const float p0 = __ldg(&P[p * 3 + 0]);
            const float p1 = __ldg(&P[p * 3 + 1]);
            const float p2 = __ldg(&P[p * 3 + 2]);
            const float q0 = -2.0f * K2 * p0;
            const float q1 = -2.0f * K2 * p1;
            const float q2 = -2.0f * K2 * p2;
            const float cc = K2 * (p0 * p0 + p1 * p1 + p2 * p2) + EPS_S;
            qk0[i] = pack2(q0, q0);
            qk1[i] = pack2(q1, q1);
            qk2[i] = pack2(q2, q2);
            cck[i] = pack2(cc, cc);
            hacc[i] = 0u;
        }
        const uint64_t K2_2 = pack2(K2, K2);

        // Local vec4 index range within this combo's image.
        const int vs = (int)(u0 & (HW4 - 1));
        const int ve = (int)(seg_end - ((unsigned long long)combo << HW4_SHIFT));

        const ulonglong2* xb = (const ulonglong2*)(x + (size_t)b * 3 * HW);

        for (int v = vs + tid; v < ve; v += THREADS) {
            const ulonglong2 c0 = xb[v];              // ch0: pixels(0,1),(2,3) packed
            const ulonglong2 c1 = xb[v + HW4];        // ch1
            const ulonglong2 c2 = xb[v + 2 * HW4];    // ch2

            // ---- pixel pair (0,1) ----
            {
                const uint64_t X0 = c0.x, X1 = c1.x, X2 = c2.x;
                uint64_t xx = mul2(X0, X0);
                xx = fma2(X1, X1, xx);
                xx = fma2(X2, X2, xx);
                const uint64_t xxk = mul2(K2_2, xx);
#pragma unroll
                for (int i = 0; i < PPT; i++) {
                    uint64_t t = add2(cck[i], xxk);
                    t = fma2(qk0[i], X0, t);
                    t = fma2(qk1[i], X1, t);
                    t = fma2(qk2[i], X2, t);
                    float ta, tb;
                    unpack2(t, ta, tb);
                    const float ra = fast_sqrt(ta);        // MUFU.SQRT
                    const float rb = fast_sqrt(tb);        // MUFU.SQRT
                    uint32_t h = cvt_f16x2(ra, rb);        // F2FP pack
                    h ^= 0x80008000u;                      // negate both halves
                    hacc[i] = hadd2u(hacc[i], ex2_h2(h));  // ONE MUFU EX2 + HADD2
                }
            }
            // ---- pixel pair (2,3) ----
            {
                const uint64_t X0 = c0.y, X1 = c1.y, X2 = c2.y;
                uint64_t xx = mul2(X0, X0);
                xx = fma2(X1, X1, xx);
                xx = fma2(X2, X2, xx);
                const uint64_t xxk = mul2(K2_2, xx);
#pragma unroll
                for (int i = 0; i < PPT; i++) {
                    uint64_t t = add2(cck[i], xxk);
                    t = fma2(qk0[i], X0, t);
                    t = fma2(qk1[i], X1, t);
                    t = fma2(qk2[i], X2, t);
                    float ta, tb;
                    unpack2(t, ta, tb);
                    const float ra = fast_sqrt(ta);
                    const float rb = fast_sqrt(tb);
                    uint32_t h = cvt_f16x2(ra, rb);
                    h ^= 0x80008000u;
                    hacc[i] = hadd2u(hacc[i], ex2_h2(h));
                }
            }
        }

        // Flush this segment into scratch: half2 -> f32, warp shuffle,
        // 1 atomic per (warp, proto).
#pragma unroll
        for (int i = 0; i < PPT; i++) {
            const __half2 h = *reinterpret_cast<const __half2*>(&hacc[i]);
            const float2 f = __half22float2(h);
            float v = f.x + f.y;
#pragma unroll
            for (int off = 16; off > 0; off >>= 1)
                v += __shfl_xor_sync(0xFFFFFFFFu, v, off);
            if (lane == 0)
                atomicAdd(&g_scratch[b * NPRO + pg * PPT + i], v);
        }

        u0 = seg_end;
    }

    // ---- last-block finisher: scale scratch into d_out, reset state ----
    __threadfence();
    __shared__ unsigned is_last;
    if (tid == 0) {
        const unsigned t = atomicAdd(&g_ticket, 1u);
        is_last = (t == NBLOCKS - 1) ? 1u : 0u;
    }
    __syncthreads();
    if (is_last) {
        __threadfence();  // all blocks' scratch atomics visible
        for (int i = tid; i < B * NPRO; i += THREADS) {
            out[i] = g_scratch[i] * (1.0f / (float)HW);
            g_scratch[i] = 0.0f;          // reset for next graph replay
        }
        __syncthreads();
        if (tid == 0) g_ticket = 0u;      // reset ticket
    }
}

extern "C" void kernel_launch(void* const* d_in, const int* in_sizes, int n_in,
                              void* d_out, int out_size) {
    const float* x = (const float*)d_in[0];
    const float* P = (const float*)d_in[1];
    float* out = (float*)d_out;

    softcount_kernel<<<NBLOCKS, THREADS>>>(x, P, out);
}